// round 1
// baseline (speedup 1.0000x reference)
#include <cuda_runtime.h>
#include <cstdint>
#include <cfloat>

#define W_TOTAL   262144
#define L_DIM     512
#define G_DIM     128
#define TILE_ROWS 128
#define NUM_TILES (W_TOTAL / TILE_ROWS)   // 2048
#define KCHUNK    64
#define NKCH      (L_DIM / KCHUNK)        // 8
#define LDA       66                      // smem A pitch (floats): 8-row stride hits distinct banks

// Scan state (device globals: no runtime allocation allowed)
__device__ float g_aggregate[NUM_TILES * G_DIM];
__device__ float g_inclusive[NUM_TILES * G_DIM];
__device__ int   g_flags[NUM_TILES];

// ---- packed f32x2 helpers -------------------------------------------------
__device__ __forceinline__ unsigned long long pack2(float x) {
    unsigned long long r;
    asm("mov.b64 %0, {%1, %1};" : "=l"(r) : "f"(x));
    return r;
}
__device__ __forceinline__ unsigned long long fma2(unsigned long long a,
                                                   unsigned long long b,
                                                   unsigned long long c) {
    unsigned long long d;
    asm("fma.rn.f32x2 %0, %1, %2, %3;" : "=l"(d) : "l"(a), "l"(b), "l"(c));
    return d;
}
__device__ __forceinline__ void unpack2(unsigned long long v, float& lo, float& hi) {
    asm("mov.b64 {%0, %1}, %2;" : "=f"(lo), "=f"(hi) : "l"(v));
}
__device__ __forceinline__ int ld_flag_cg(const int* p) {
    int f;
    asm volatile("ld.global.cg.b32 %0, [%1];" : "=r"(f) : "l"(p));
    return f;
}
__device__ __forceinline__ float ld_f_cg(const float* p) {
    float f;
    asm volatile("ld.global.cg.f32 %0, [%1];" : "=f"(f) : "l"(p));
    return f;
}

__global__ void init_flags_kernel() {
    int i = blockIdx.x * blockDim.x + threadIdx.x;
    if (i < NUM_TILES) g_flags[i] = 0;
}

// ---- fused GEMM + cummax (decoupled lookback) ------------------------------
__global__ void __launch_bounds__(256, 2)
key_pool_kernel(const float* __restrict__ A,      // [W, L]
                const float* __restrict__ gfeat,  // [G]
                const float* __restrict__ W1,     // [L, G]
                const float* __restrict__ b1,     // [G]
                float* __restrict__ out,          // [W*G (+ G)]
                int write_tail) {
    extern __shared__ float sm[];
    float* As   = sm;                       // [128][LDA]
    float* Ws   = As + TILE_ROWS * LDA;     // [64][128]
    float* Sseg = Ws + KCHUNK * G_DIM;      // [16][128]
    float* Spre = Sseg + 16 * G_DIM;        // [128]
    __shared__ int s_state;

    const int tid  = threadIdx.x;
    const int cg   = tid & 15;   // column group: cols cg*8 .. cg*8+7
    const int rg   = tid >> 4;   // row group:    rows rg*8 .. rg*8+7
    const int tile = blockIdx.x;

    const float* Ablk = A + (size_t)tile * TILE_ROWS * L_DIM;
    const float4* Ablk4 = (const float4*)Ablk;   // 128 float4 per row
    const float4* W14   = (const float4*)W1;     // 32 float4 per row

    unsigned long long acc[8][4];
    #pragma unroll
    for (int r = 0; r < 8; ++r)
        #pragma unroll
        for (int j = 0; j < 4; ++j) acc[r][j] = 0ull;

    // ---- GEMM: 8 K-chunks of 64 ----
    for (int kc = 0; kc < NKCH; ++kc) {
        // Stage A chunk [128][64] -> As[row][k] (pitch LDA)
        #pragma unroll
        for (int i = 0; i < 8; ++i) {
            int e   = tid + i * 256;     // 0..2047 float4s
            int row = e >> 4;
            int k4  = e & 15;
            float4 v = __ldg(&Ablk4[row * 128 + kc * 16 + k4]);
            float* d = &As[row * LDA + k4 * 4];
            ((float2*)d)[0] = make_float2(v.x, v.y);
            ((float2*)d)[1] = make_float2(v.z, v.w);
        }
        // Stage W chunk [64][128] (contiguous)
        #pragma unroll
        for (int i = 0; i < 8; ++i) {
            int e = tid + i * 256;       // 0..2047 float4s
            ((float4*)Ws)[e] = __ldg(&W14[kc * 2048 + e]);
        }
        __syncthreads();

        #pragma unroll 4
        for (int k = 0; k < KCHUNK; ++k) {
            const ulonglong2 wA = *(const ulonglong2*)&Ws[k * G_DIM + cg * 8];
            const ulonglong2 wB = *(const ulonglong2*)&Ws[k * G_DIM + cg * 8 + 4];
            unsigned long long w0 = wA.x, w1 = wA.y, w2 = wB.x, w3 = wB.y;
            #pragma unroll
            for (int r = 0; r < 8; ++r) {
                float a = As[(rg * 8 + r) * LDA + k];
                unsigned long long a2 = pack2(a);
                acc[r][0] = fma2(a2, w0, acc[r][0]);
                acc[r][1] = fma2(a2, w1, acc[r][1]);
                acc[r][2] = fma2(a2, w2, acc[r][2]);
                acc[r][3] = fma2(a2, w3, acc[r][3]);
            }
        }
        __syncthreads();
    }

    // ---- epilogue: bias + in-thread cummax ----
    float bc[8];
    #pragma unroll
    for (int j = 0; j < 8; ++j) bc[j] = __ldg(&b1[cg * 8 + j]);

    float v[8][8];
    #pragma unroll
    for (int r = 0; r < 8; ++r)
        #pragma unroll
        for (int j = 0; j < 4; ++j) {
            float lo, hi;
            unpack2(acc[r][j], lo, hi);
            v[r][2 * j]     = lo + bc[2 * j];
            v[r][2 * j + 1] = hi + bc[2 * j + 1];
        }
    #pragma unroll
    for (int r = 1; r < 8; ++r)
        #pragma unroll
        for (int j = 0; j < 8; ++j)
            v[r][j] = fmaxf(v[r][j], v[r - 1][j]);

    // segment (8-row) aggregates into smem
    #pragma unroll
    for (int j = 0; j < 8; ++j)
        Sseg[rg * G_DIM + cg * 8 + j] = v[7][j];
    __syncthreads();

    // per-thread exclusive prefix over row-groups
    float pre8[8];
    #pragma unroll
    for (int j = 0; j < 8; ++j) pre8[j] = -FLT_MAX;
    for (int q = 0; q < rg; ++q)
        #pragma unroll
        for (int j = 0; j < 8; ++j)
            pre8[j] = fmaxf(pre8[j], Sseg[q * G_DIM + cg * 8 + j]);

    // ---- tile aggregate publish + decoupled lookback ----
    float incl = -FLT_MAX;
    if (tile == 0) {
        if (tid < G_DIM) {
            float a = -FLT_MAX;
            #pragma unroll
            for (int q = 0; q < 16; ++q) a = fmaxf(a, Sseg[q * G_DIM + tid]);
            float run = __ldg(&gfeat[tid]);   // seed with global feature
            incl = fmaxf(a, run);
            g_inclusive[tid] = incl;
            Spre[tid] = run;
        }
        __threadfence();
        __syncthreads();
        if (tid == 0) atomicExch(&g_flags[0], 2);
    } else {
        float a = -FLT_MAX;
        if (tid < G_DIM) {
            #pragma unroll
            for (int q = 0; q < 16; ++q) a = fmaxf(a, Sseg[q * G_DIM + tid]);
            g_aggregate[(size_t)tile * G_DIM + tid] = a;
        }
        __threadfence();
        __syncthreads();
        if (tid == 0) atomicExch(&g_flags[tile], 1);

        float run = -FLT_MAX;
        int p = tile - 1;
        while (true) {
            if (tid == 0) {
                int f = ld_flag_cg(&g_flags[p]);
                while (f == 0) { __nanosleep(50); f = ld_flag_cg(&g_flags[p]); }
                s_state = f;
            }
            __syncthreads();
            int f = s_state;
            if (tid < G_DIM) {
                const float* src = (f == 2) ? &g_inclusive[(size_t)p * G_DIM]
                                            : &g_aggregate[(size_t)p * G_DIM];
                run = fmaxf(run, ld_f_cg(&src[tid]));
            }
            __syncthreads();   // protect s_state reuse
            if (f == 2) break;
            --p;
        }
        if (tid < G_DIM) {
            incl = fmaxf(run, a);
            g_inclusive[(size_t)tile * G_DIM + tid] = incl;
            Spre[tid] = run;
        }
        __threadfence();
        __syncthreads();
        if (tid == 0) atomicExch(&g_flags[tile], 2);
    }
    __syncthreads();

    // ---- combine and store ----
    #pragma unroll
    for (int j = 0; j < 8; ++j)
        pre8[j] = fmaxf(pre8[j], Spre[cg * 8 + j]);

    #pragma unroll
    for (int r = 0; r < 8; ++r) {
        float4 o0, o1;
        o0.x = fmaxf(v[r][0], pre8[0]);
        o0.y = fmaxf(v[r][1], pre8[1]);
        o0.z = fmaxf(v[r][2], pre8[2]);
        o0.w = fmaxf(v[r][3], pre8[3]);
        o1.x = fmaxf(v[r][4], pre8[4]);
        o1.y = fmaxf(v[r][5], pre8[5]);
        o1.z = fmaxf(v[r][6], pre8[6]);
        o1.w = fmaxf(v[r][7], pre8[7]);
        size_t row = (size_t)tile * TILE_ROWS + rg * 8 + r;
        float4* dst = (float4*)&out[row * G_DIM + cg * 8];
        dst[0] = o0;
        dst[1] = o1;
    }

    // final row == new global feature (appended after [W,G] block)
    if (write_tail && tile == NUM_TILES - 1 && tid < G_DIM)
        out[(size_t)W_TOTAL * G_DIM + tid] = incl;
}

extern "C" void kernel_launch(void* const* d_in, const int* in_sizes, int n_in,
                              void* d_out, int out_size) {
    const float* local = (const float*)d_in[0];  // [262144, 512]
    const float* gfeat = (const float*)d_in[1];  // [1, 128]
    const float* W1    = (const float*)d_in[2];  // [512, 128]
    const float* b1    = (const float*)d_in[3];  // [128]
    float* out = (float*)d_out;

    const int smem_bytes =
        (TILE_ROWS * LDA + KCHUNK * G_DIM + 16 * G_DIM + G_DIM) * (int)sizeof(float);
    static int configured = 0;
    if (!configured) {
        cudaFuncSetAttribute(key_pool_kernel,
                             cudaFuncAttributeMaxDynamicSharedMemorySize, smem_bytes);
        configured = 1;
    }

    int write_tail = (out_size >= W_TOTAL * G_DIM + G_DIM) ? 1 : 0;

    init_flags_kernel<<<2, 1024>>>();
    key_pool_kernel<<<NUM_TILES, 256, smem_bytes>>>(local, gfeat, W1, b1, out, write_tail);
}

// round 3
// speedup vs baseline: 2.0805x; 2.0805x over previous
#include <cuda_runtime.h>
#include <cuda_bf16.h>
#include <cstdint>
#include <cfloat>

#define W_TOTAL   262144
#define L_DIM     512
#define G_DIM     128
#define TILE_ROWS 128
#define NUM_TILES (W_TOTAL / TILE_ROWS)   // 2048
#define KCHUNK    64
#define NKCH      (L_DIM / KCHUNK)        // 8

// ---- smem layout (bytes), dynamic smem only (no static __shared__) ----
#define OFF_AHI    0
#define OFF_ALO    16384
#define OFF_BHI    32768
#define OFF_BLO    49152              // GEMM region total 64 KB
#define OFF_SSC    0                  // epilogue reuse: float[128][132]
#define SSC_PITCH  132
#define OFF_SB     67584              // bias 128 f32
#define OFF_SPRE   68096              // tile prefix 128 f32
#define OFF_STATE  68608              // lookback state flag (int)
#define SMEM_TOTAL 68640

// device globals (no runtime allocation allowed)
__device__ __nv_bfloat16 g_Whi[G_DIM * L_DIM];  // [n][k] k-major
__device__ __nv_bfloat16 g_Wlo[G_DIM * L_DIM];
__device__ float g_aggregate[NUM_TILES * G_DIM];
__device__ float g_inclusive[NUM_TILES * G_DIM];
__device__ int   g_flags[NUM_TILES];

#define SW128(o) ((o) ^ (((o) >> 3) & 0x70))

// ---- PTX helpers ----
__device__ __forceinline__ uint32_t smem_u32(const void* p) {
    uint32_t a;
    asm("{ .reg .u64 t; cvta.to.shared.u64 t, %1; cvt.u32.u64 %0, t; }" : "=r"(a) : "l"(p));
    return a;
}
__device__ __forceinline__ void ldsm_x4(uint32_t& r0, uint32_t& r1, uint32_t& r2,
                                        uint32_t& r3, uint32_t addr) {
    asm volatile("ldmatrix.sync.aligned.m8n8.x4.shared.b16 {%0,%1,%2,%3}, [%4];"
                 : "=r"(r0), "=r"(r1), "=r"(r2), "=r"(r3) : "r"(addr));
}
__device__ __forceinline__ void mma_bf16(float* c, const uint32_t* a, uint32_t b0, uint32_t b1) {
    asm volatile(
        "mma.sync.aligned.m16n8k16.row.col.f32.bf16.bf16.f32 "
        "{%0,%1,%2,%3}, {%4,%5,%6,%7}, {%8,%9}, {%0,%1,%2,%3};"
        : "+f"(c[0]), "+f"(c[1]), "+f"(c[2]), "+f"(c[3])
        : "r"(a[0]), "r"(a[1]), "r"(a[2]), "r"(a[3]), "r"(b0), "r"(b1));
}
__device__ __forceinline__ int ld_flag_cg(const int* p) {
    int f; asm volatile("ld.global.cg.b32 %0, [%1];" : "=r"(f) : "l"(p)); return f;
}
__device__ __forceinline__ float ld_f_cg(const float* p) {
    float f; asm volatile("ld.global.cg.f32 %0, [%1];" : "=f"(f) : "l"(p)); return f;
}

// ---- prep kernels ----
__global__ void init_flags_kernel() {
    int i = blockIdx.x * blockDim.x + threadIdx.x;
    if (i < NUM_TILES) g_flags[i] = 0;
}
__global__ void prep_w_kernel(const float* __restrict__ W1) {   // W1: [512][128]
    int idx = blockIdx.x * 256 + threadIdx.x;                   // 65536
    int k = idx >> 7, n = idx & 127;
    float w = W1[idx];
    __nv_bfloat16 h = __float2bfloat16(w);
    float r = w - __bfloat162float(h);
    g_Whi[n * L_DIM + k] = h;
    g_Wlo[n * L_DIM + k] = __float2bfloat16(r);
}

// ---- main fused kernel: HMMA GEMM + cummax lookback ----
__global__ void __launch_bounds__(256, 2)
key_pool_mma(const float* __restrict__ A,      // [W, L]
             const float* __restrict__ gfeat,  // [G]
             const float* __restrict__ b1,     // [G]
             float* __restrict__ out, int write_tail) {
    extern __shared__ char sm[];
    const uint32_t smb = smem_u32(sm);
    float* Ssc   = (float*)(sm + OFF_SSC);
    float* Sb    = (float*)(sm + OFF_SB);
    float* Spre  = (float*)(sm + OFF_SPRE);
    int*   Sstat = (int*)(sm + OFF_STATE);

    const int tid  = threadIdx.x;
    const int wid  = tid >> 5;
    const int lane = tid & 31;
    const int tile = blockIdx.x;

    const int Rw = (wid & 3) * 32;   // warp row base
    const int Cw = (wid >> 2) * 64;  // warp col base

    const float4* A4 = (const float4*)(A + (size_t)tile * TILE_ROWS * L_DIM);
    const uint4*  BH = (const uint4*)g_Whi;   // [128][64] uint4 (512 bf16/row)
    const uint4*  BL = (const uint4*)g_Wlo;

    float acc[2][8][4];
    #pragma unroll
    for (int t = 0; t < 2; ++t)
        #pragma unroll
        for (int n = 0; n < 8; ++n)
            #pragma unroll
            for (int j = 0; j < 4; ++j) acc[t][n][j] = 0.f;

    // ldmatrix source offsets (byte, pre-swizzle) — constant per thread except k16 step
    // A: row = Rw + t*16 + (lane&15), kb = (lane>>4)*16
    // B(x4, two n-tiles): n = Cw + nt2*16 + ((lane>>4)&1)*8 + (lane&7), kb = ((lane>>3)&1)*16
    const int a_row = (lane & 15);
    const int a_kb  = (lane >> 4) << 4;
    const int b_nrow = ((lane >> 4) & 1) * 8 + (lane & 7);
    const int b_kb   = ((lane >> 3) & 1) << 4;

    for (int kc = 0; kc < NKCH; ++kc) {
        // ---- stage A chunk [128][64] fp32 -> bf16 hi/lo, SW128 ----
        #pragma unroll
        for (int i = 0; i < 8; ++i) {
            int e = tid + i * 256;               // 0..2047 float4
            int r = e >> 4, q = e & 15;
            float4 v = __ldg(&A4[r * 128 + kc * 16 + q]);
            __nv_bfloat162 h01 = __float22bfloat162_rn(make_float2(v.x, v.y));
            __nv_bfloat162 h23 = __float22bfloat162_rn(make_float2(v.z, v.w));
            float2 f01 = __bfloat1622float2(h01);
            float2 f23 = __bfloat1622float2(h23);
            __nv_bfloat162 l01 = __float22bfloat162_rn(make_float2(v.x - f01.x, v.y - f01.y));
            __nv_bfloat162 l23 = __float22bfloat162_rn(make_float2(v.z - f23.x, v.w - f23.y));
            uint32_t off = SW128((uint32_t)(r * 128 + q * 8));
            *(uint2*)(sm + OFF_AHI + off) = make_uint2(*(uint32_t*)&h01, *(uint32_t*)&h23);
            *(uint2*)(sm + OFF_ALO + off) = make_uint2(*(uint32_t*)&l01, *(uint32_t*)&l23);
        }
        // ---- stage B chunk [128n][64k] bf16 hi/lo, SW128 ----
        #pragma unroll
        for (int i = 0; i < 4; ++i) {
            int e = tid + i * 256;               // 0..1023 uint4
            int n = e >> 3, u = e & 7;
            uint32_t off = SW128((uint32_t)(n * 128 + u * 16));
            *(uint4*)(sm + OFF_BHI + off) = __ldg(&BH[n * 64 + kc * 8 + u]);
            *(uint4*)(sm + OFF_BLO + off) = __ldg(&BL[n * 64 + kc * 8 + u]);
        }
        __syncthreads();

        // ---- MMA over 4 k16 steps ----
        #pragma unroll
        for (int k16 = 0; k16 < 4; ++k16) {
            const int kstep = k16 * 32;
            uint32_t ah[2][4], al[2][4];
            #pragma unroll
            for (int t = 0; t < 2; ++t) {
                uint32_t offA = (uint32_t)((Rw + t * 16 + a_row) * 128 + kstep + a_kb);
                ldsm_x4(ah[t][0], ah[t][1], ah[t][2], ah[t][3], smb + OFF_AHI + SW128(offA));
                ldsm_x4(al[t][0], al[t][1], al[t][2], al[t][3], smb + OFF_ALO + SW128(offA));
            }
            #pragma unroll
            for (int nt2 = 0; nt2 < 4; ++nt2) {
                uint32_t offB = (uint32_t)((Cw + nt2 * 16 + b_nrow) * 128 + kstep + b_kb);
                uint32_t bh[4], bl[4];
                ldsm_x4(bh[0], bh[1], bh[2], bh[3], smb + OFF_BHI + SW128(offB));
                ldsm_x4(bl[0], bl[1], bl[2], bl[3], smb + OFF_BLO + SW128(offB));
                #pragma unroll
                for (int half = 0; half < 2; ++half) {
                    const int nt = nt2 * 2 + half;
                    #pragma unroll
                    for (int t = 0; t < 2; ++t) {
                        mma_bf16(acc[t][nt], ah[t], bh[half * 2], bh[half * 2 + 1]);
                        mma_bf16(acc[t][nt], ah[t], bl[half * 2], bl[half * 2 + 1]);
                        mma_bf16(acc[t][nt], al[t], bh[half * 2], bh[half * 2 + 1]);
                    }
                }
            }
        }
        __syncthreads();
    }

    // ---- epilogue: dump + bias into smem [128][SSC_PITCH] ----
    if (tid < G_DIM) Sb[tid] = __ldg(&b1[tid]);
    __syncthreads();

    const int g = lane >> 2;
    const int cq = (lane & 3) * 2;
    #pragma unroll
    for (int t = 0; t < 2; ++t) {
        #pragma unroll
        for (int nt = 0; nt < 8; ++nt) {
            int col = Cw + nt * 8 + cq;
            float2 b2 = *(float2*)&Sb[col];
            int r0 = Rw + t * 16 + g;
            *(float2*)&Ssc[r0 * SSC_PITCH + col] =
                make_float2(acc[t][nt][0] + b2.x, acc[t][nt][1] + b2.y);
            *(float2*)&Ssc[(r0 + 8) * SSC_PITCH + col] =
                make_float2(acc[t][nt][2] + b2.x, acc[t][nt][3] + b2.y);
        }
    }
    __syncthreads();

    // ---- column cummax over 128 rows: warp w handles 16 columns ----
    {
        const int cw = wid * 16;
        float carry[16];
        #pragma unroll
        for (int j = 0; j < 16; ++j) carry[j] = -FLT_MAX;
        for (int rb = 0; rb < 4; ++rb) {
            int row = rb * 32 + lane;
            float v[16];
            #pragma unroll
            for (int q = 0; q < 4; ++q) {
                float4 x = *(float4*)&Ssc[row * SSC_PITCH + cw + q * 4];
                v[q * 4 + 0] = x.x; v[q * 4 + 1] = x.y;
                v[q * 4 + 2] = x.z; v[q * 4 + 3] = x.w;
            }
            #pragma unroll
            for (int d = 1; d < 32; d <<= 1) {
                #pragma unroll
                for (int j = 0; j < 16; ++j) {
                    float tshf = __shfl_up_sync(0xffffffffu, v[j], d);
                    if (lane >= d) v[j] = fmaxf(v[j], tshf);
                }
            }
            #pragma unroll
            for (int j = 0; j < 16; ++j) v[j] = fmaxf(v[j], carry[j]);
            #pragma unroll
            for (int q = 0; q < 4; ++q) {
                float4 x = make_float4(v[q * 4], v[q * 4 + 1], v[q * 4 + 2], v[q * 4 + 3]);
                *(float4*)&Ssc[row * SSC_PITCH + cw + q * 4] = x;
            }
            #pragma unroll
            for (int j = 0; j < 16; ++j) carry[j] = __shfl_sync(0xffffffffu, v[j], 31);
        }
    }
    __syncthreads();

    // ---- decoupled lookback over tiles ----
    float incl = -FLT_MAX;
    if (tile == 0) {
        if (tid < G_DIM) {
            float a = Ssc[127 * SSC_PITCH + tid];
            float run = __ldg(&gfeat[tid]);       // seed with global feature
            incl = fmaxf(a, run);
            g_inclusive[tid] = incl;
            Spre[tid] = run;
        }
        __threadfence();
        __syncthreads();
        if (tid == 0) atomicExch(&g_flags[0], 2);
    } else {
        float a = -FLT_MAX;
        if (tid < G_DIM) {
            a = Ssc[127 * SSC_PITCH + tid];
            g_aggregate[(size_t)tile * G_DIM + tid] = a;
        }
        __threadfence();
        __syncthreads();
        if (tid == 0) atomicExch(&g_flags[tile], 1);

        float run = -FLT_MAX;
        int p = tile - 1;
        while (true) {
            if (tid == 0) {
                int f = ld_flag_cg(&g_flags[p]);
                while (f == 0) { __nanosleep(50); f = ld_flag_cg(&g_flags[p]); }
                *Sstat = f;
            }
            __syncthreads();
            int f = *Sstat;
            if (tid < G_DIM) {
                const float* src = (f == 2) ? &g_inclusive[(size_t)p * G_DIM]
                                            : &g_aggregate[(size_t)p * G_DIM];
                run = fmaxf(run, ld_f_cg(&src[tid]));
            }
            __syncthreads();
            if (f == 2) break;
            --p;
        }
        if (tid < G_DIM) {
            incl = fmaxf(run, a);
            g_inclusive[(size_t)tile * G_DIM + tid] = incl;
            Spre[tid] = run;
        }
        __threadfence();
        __syncthreads();
        if (tid == 0) atomicExch(&g_flags[tile], 2);
    }
    __syncthreads();

    // ---- combine with tile prefix, stream out ----
    float4* out4 = (float4*)(out + (size_t)tile * TILE_ROWS * G_DIM);
    #pragma unroll
    for (int i = 0; i < 16; ++i) {
        int e = tid + i * 256;                    // 0..4095 float4
        int r = e >> 5, c4 = e & 31;
        const float* s  = &Ssc[r * SSC_PITCH + c4 * 4];
        const float* pp = &Spre[c4 * 4];
        float4 o;
        o.x = fmaxf(s[0], pp[0]);
        o.y = fmaxf(s[1], pp[1]);
        o.z = fmaxf(s[2], pp[2]);
        o.w = fmaxf(s[3], pp[3]);
        out4[e] = o;
    }
    if (write_tail && tile == NUM_TILES - 1 && tid < G_DIM)
        out[(size_t)W_TOTAL * G_DIM + tid] = incl;
}

extern "C" void kernel_launch(void* const* d_in, const int* in_sizes, int n_in,
                              void* d_out, int out_size) {
    const float* local = (const float*)d_in[0];  // [262144, 512]
    const float* gfeat = (const float*)d_in[1];  // [1, 128]
    const float* W1    = (const float*)d_in[2];  // [512, 128]
    const float* b1    = (const float*)d_in[3];  // [128]
    float* out = (float*)d_out;

    static int configured = 0;
    if (!configured) {
        cudaFuncSetAttribute(key_pool_mma,
                             cudaFuncAttributeMaxDynamicSharedMemorySize, SMEM_TOTAL);
        configured = 1;
    }
    int write_tail = (out_size >= W_TOTAL * G_DIM + G_DIM) ? 1 : 0;

    init_flags_kernel<<<2, 1024>>>();
    prep_w_kernel<<<256, 256>>>(W1);
    key_pool_mma<<<NUM_TILES, 256, SMEM_TOTAL>>>(local, gfeat, b1, out, write_tail);
}

// round 4
// speedup vs baseline: 2.6735x; 1.2850x over previous
#include <cuda_runtime.h>
#include <cuda_fp16.h>
#include <cstdint>
#include <cfloat>

#define W_TOTAL   262144
#define L_DIM     512
#define G_DIM     128
#define TILE_ROWS 128
#define NUM_TILES (W_TOTAL / TILE_ROWS)   // 2048
#define NKCH      8                       // K chunks of 64

// ---- smem layout (bytes), dynamic smem only ----
#define OFF_AH0    0                  // A fp16 [128][64], 16 KB
#define OFF_AH1    16384
#define OFF_B0     32768              // B fp16 [128n][64k], 16 KB
#define OFF_B1     49152              // GEMM region ends at 65536
#define OFF_SSC    0                  // epilogue reuse: float[128][132]
#define SSC_PITCH  132
#define OFF_SB     67584              // bias 128 f32
#define OFF_SPRE   68096              // tile prefix 128 f32
#define OFF_STATE  68608              // lookback state flag
#define SMEM_TOTAL 68640

// device globals (no runtime allocation allowed)
__device__ __half g_Wh[G_DIM * L_DIM];          // W1^T as fp16, [n][k] k-major
__device__ float  g_aggregate[NUM_TILES * G_DIM];
__device__ float  g_inclusive[NUM_TILES * G_DIM];
__device__ int    g_flags[NUM_TILES];

#define SW128(o) ((o) ^ (((o) >> 3) & 0x70))

// ---- PTX helpers ----
__device__ __forceinline__ uint32_t smem_u32(const void* p) {
    uint32_t a;
    asm("{ .reg .u64 t; cvta.to.shared.u64 t, %1; cvt.u32.u64 %0, t; }" : "=r"(a) : "l"(p));
    return a;
}
__device__ __forceinline__ void ldsm_x4(uint32_t& r0, uint32_t& r1, uint32_t& r2,
                                        uint32_t& r3, uint32_t addr) {
    asm volatile("ldmatrix.sync.aligned.m8n8.x4.shared.b16 {%0,%1,%2,%3}, [%4];"
                 : "=r"(r0), "=r"(r1), "=r"(r2), "=r"(r3) : "r"(addr));
}
__device__ __forceinline__ void mma_f16(float* c, const uint32_t* a, uint32_t b0, uint32_t b1) {
    asm volatile(
        "mma.sync.aligned.m16n8k16.row.col.f32.f16.f16.f32 "
        "{%0,%1,%2,%3}, {%4,%5,%6,%7}, {%8,%9}, {%0,%1,%2,%3};"
        : "+f"(c[0]), "+f"(c[1]), "+f"(c[2]), "+f"(c[3])
        : "r"(a[0]), "r"(a[1]), "r"(a[2]), "r"(a[3]), "r"(b0), "r"(b1));
}
__device__ __forceinline__ void cp_async16(uint32_t dst, const void* src) {
    asm volatile("cp.async.cg.shared.global [%0], [%1], 16;" :: "r"(dst), "l"(src));
}
#define CP_COMMIT() asm volatile("cp.async.commit_group;" ::: "memory")
#define CP_WAIT0()  asm volatile("cp.async.wait_group 0;" ::: "memory")

__device__ __forceinline__ int ld_flag_cg(const int* p) {
    int f; asm volatile("ld.global.cg.b32 %0, [%1];" : "=r"(f) : "l"(p)); return f;
}
__device__ __forceinline__ float ld_f_cg(const float* p) {
    float f; asm volatile("ld.global.cg.f32 %0, [%1];" : "=f"(f) : "l"(p)); return f;
}

// ---- merged prep kernel (1 launch): W1 -> fp16 transpose, zero flags ----
__global__ void prep_kernel(const float* __restrict__ W1) {   // W1: [512][128]
    int idx = blockIdx.x * 256 + threadIdx.x;                 // 65536
    int k = idx >> 7, n = idx & 127;
    g_Wh[n * L_DIM + k] = __float2half_rn(W1[idx]);
    if (idx < NUM_TILES) g_flags[idx] = 0;
}

// ---- main fused kernel: pipelined fp16 HMMA GEMM + cummax lookback ----
__global__ void __launch_bounds__(256, 2)
key_pool_mma(const float* __restrict__ A,      // [W, L]
             const float* __restrict__ gfeat,  // [G]
             const float* __restrict__ b1,     // [G]
             float* __restrict__ out, int write_tail) {
    extern __shared__ char sm[];
    const uint32_t smb = smem_u32(sm);
    float* Ssc   = (float*)(sm + OFF_SSC);
    float* Sb    = (float*)(sm + OFF_SB);
    float* Spre  = (float*)(sm + OFF_SPRE);
    int*   Sstat = (int*)(sm + OFF_STATE);

    const int tid  = threadIdx.x;
    const int wid  = tid >> 5;
    const int lane = tid & 31;
    const int tile = blockIdx.x;

    const int Rw = (wid & 3) * 32;   // warp row base
    const int Cw = (wid >> 2) * 64;  // warp col base

    const float4* A4 = (const float4*)(A + (size_t)tile * TILE_ROWS * L_DIM);

    // staging coordinates (constant per thread)
    const int sa_r = tid >> 1;            // unused form; use per-i below
    (void)sa_r;

    float acc[2][8][4];
    #pragma unroll
    for (int t = 0; t < 2; ++t)
        #pragma unroll
        for (int n = 0; n < 8; ++n)
            #pragma unroll
            for (int j = 0; j < 4; ++j) acc[t][n][j] = 0.f;

    // ldmatrix per-thread offsets
    const int a_row  = (lane & 15);
    const int a_kb   = (lane >> 4) << 4;
    const int b_nrow = ((lane >> 4) & 1) * 8 + (lane & 7);
    const int b_kb   = ((lane >> 3) & 1) << 4;

    // ---- prologue: LDG A(0) into regs, cp.async B(0) ----
    float4 ra[8];
    #pragma unroll
    for (int i = 0; i < 8; ++i) {
        int e = tid + i * 256, r = e >> 4, q = e & 15;
        ra[i] = __ldg(&A4[r * 128 + q]);
    }
    {
        const __half* Wh = g_Wh;
        #pragma unroll
        for (int i = 0; i < 4; ++i) {
            int e = tid + i * 256, n = e >> 3, u = e & 7;
            cp_async16(smb + OFF_B0 + SW128((uint32_t)(n * 128 + u * 16)),
                       Wh + n * L_DIM + u * 8);
        }
        CP_COMMIT();
    }

    // ---- pipelined mainloop: one __syncthreads per chunk ----
    #pragma unroll
    for (int kc = 0; kc < NKCH; ++kc) {
        char* ahp = sm + ((kc & 1) ? OFF_AH1 : OFF_AH0);
        const uint32_t ahb = smb + ((kc & 1) ? OFF_AH1 : OFF_AH0);
        const uint32_t bbb = smb + ((kc & 1) ? OFF_B1 : OFF_B0);

        // convert + STS A(kc) from regs (safe: Ah[kc&1] last read by MMA(kc-2))
        #pragma unroll
        for (int i = 0; i < 8; ++i) {
            int e = tid + i * 256, r = e >> 4, q = e & 15;
            __half2 h01 = __float22half2_rn(make_float2(ra[i].x, ra[i].y));
            __half2 h23 = __float22half2_rn(make_float2(ra[i].z, ra[i].w));
            *(uint2*)(ahp + SW128((uint32_t)(r * 128 + q * 8))) =
                make_uint2(*(uint32_t*)&h01, *(uint32_t*)&h23);
        }
        // prefetch A(kc+1) into the same regs (WAR after converts)
        if (kc < NKCH - 1) {
            #pragma unroll
            for (int i = 0; i < 8; ++i) {
                int e = tid + i * 256, r = e >> 4, q = e & 15;
                ra[i] = __ldg(&A4[r * 128 + (kc + 1) * 16 + q]);
            }
        }

        CP_WAIT0();          // B(kc) landed (this thread)
        __syncthreads();     // all threads: B(kc)+A(kc) staged, MMA(kc-1) done

        // prefetch B(kc+1) into the other buffer (safe: MMA(kc-1) done)
        if (kc < NKCH - 1) {
            const uint32_t bnext = smb + (((kc + 1) & 1) ? OFF_B1 : OFF_B0);
            const __half* Wh = g_Wh;
            #pragma unroll
            for (int i = 0; i < 4; ++i) {
                int e = tid + i * 256, n = e >> 3, u = e & 7;
                cp_async16(bnext + SW128((uint32_t)(n * 128 + u * 16)),
                           Wh + n * L_DIM + (kc + 1) * 64 + u * 8);
            }
            CP_COMMIT();
        }

        // ---- MMA over 4 k16 steps ----
        #pragma unroll
        for (int k16 = 0; k16 < 4; ++k16) {
            const int kstep = k16 * 32;
            uint32_t ah[2][4];
            #pragma unroll
            for (int t = 0; t < 2; ++t) {
                uint32_t offA = (uint32_t)((Rw + t * 16 + a_row) * 128 + kstep + a_kb);
                ldsm_x4(ah[t][0], ah[t][1], ah[t][2], ah[t][3], ahb + SW128(offA));
            }
            #pragma unroll
            for (int nt2 = 0; nt2 < 4; ++nt2) {
                uint32_t offB = (uint32_t)((Cw + nt2 * 16 + b_nrow) * 128 + kstep + b_kb);
                uint32_t bf[4];
                ldsm_x4(bf[0], bf[1], bf[2], bf[3], bbb + SW128(offB));
                #pragma unroll
                for (int half = 0; half < 2; ++half) {
                    const int nt = nt2 * 2 + half;
                    #pragma unroll
                    for (int t = 0; t < 2; ++t)
                        mma_f16(acc[t][nt], ah[t], bf[half * 2], bf[half * 2 + 1]);
                }
            }
        }
    }

    // ---- epilogue: bias + dump into smem [128][SSC_PITCH] ----
    if (tid < G_DIM) Sb[tid] = __ldg(&b1[tid]);
    __syncthreads();     // also guarantees MMA(7) done before Ssc overwrites GEMM smem

    const int g  = lane >> 2;
    const int cq = (lane & 3) * 2;
    #pragma unroll
    for (int t = 0; t < 2; ++t) {
        #pragma unroll
        for (int nt = 0; nt < 8; ++nt) {
            int col = Cw + nt * 8 + cq;
            float2 b2 = *(float2*)&Sb[col];
            int r0 = Rw + t * 16 + g;
            *(float2*)&Ssc[r0 * SSC_PITCH + col] =
                make_float2(acc[t][nt][0] + b2.x, acc[t][nt][1] + b2.y);
            *(float2*)&Ssc[(r0 + 8) * SSC_PITCH + col] =
                make_float2(acc[t][nt][2] + b2.x, acc[t][nt][3] + b2.y);
        }
    }
    __syncthreads();

    // ---- column cummax over 128 rows: warp w handles 16 columns ----
    {
        const int cw = wid * 16;
        float carry[16];
        #pragma unroll
        for (int j = 0; j < 16; ++j) carry[j] = -FLT_MAX;
        for (int rb = 0; rb < 4; ++rb) {
            int row = rb * 32 + lane;
            float v[16];
            #pragma unroll
            for (int q = 0; q < 4; ++q) {
                float4 x = *(float4*)&Ssc[row * SSC_PITCH + cw + q * 4];
                v[q * 4 + 0] = x.x; v[q * 4 + 1] = x.y;
                v[q * 4 + 2] = x.z; v[q * 4 + 3] = x.w;
            }
            #pragma unroll
            for (int d = 1; d < 32; d <<= 1) {
                #pragma unroll
                for (int j = 0; j < 16; ++j) {
                    float tshf = __shfl_up_sync(0xffffffffu, v[j], d);
                    if (lane >= d) v[j] = fmaxf(v[j], tshf);
                }
            }
            #pragma unroll
            for (int j = 0; j < 16; ++j) v[j] = fmaxf(v[j], carry[j]);
            #pragma unroll
            for (int q = 0; q < 4; ++q) {
                float4 x = make_float4(v[q * 4], v[q * 4 + 1], v[q * 4 + 2], v[q * 4 + 3]);
                *(float4*)&Ssc[row * SSC_PITCH + cw + q * 4] = x;
            }
            #pragma unroll
            for (int j = 0; j < 16; ++j) carry[j] = __shfl_sync(0xffffffffu, v[j], 31);
        }
    }
    __syncthreads();

    // ---- decoupled lookback over tiles ----
    float incl = -FLT_MAX;
    if (tile == 0) {
        if (tid < G_DIM) {
            float a = Ssc[127 * SSC_PITCH + tid];
            float run = __ldg(&gfeat[tid]);       // seed with global feature
            incl = fmaxf(a, run);
            g_inclusive[tid] = incl;
            Spre[tid] = run;
        }
        __threadfence();
        __syncthreads();
        if (tid == 0) atomicExch(&g_flags[0], 2);
    } else {
        float a = -FLT_MAX;
        if (tid < G_DIM) {
            a = Ssc[127 * SSC_PITCH + tid];
            g_aggregate[(size_t)tile * G_DIM + tid] = a;
        }
        __threadfence();
        __syncthreads();
        if (tid == 0) atomicExch(&g_flags[tile], 1);

        float run = -FLT_MAX;
        int p = tile - 1;
        while (true) {
            if (tid == 0) {
                int f = ld_flag_cg(&g_flags[p]);
                while (f == 0) { __nanosleep(50); f = ld_flag_cg(&g_flags[p]); }
                *Sstat = f;
            }
            __syncthreads();
            int f = *Sstat;
            if (tid < G_DIM) {
                const float* src = (f == 2) ? &g_inclusive[(size_t)p * G_DIM]
                                            : &g_aggregate[(size_t)p * G_DIM];
                run = fmaxf(run, ld_f_cg(&src[tid]));
            }
            __syncthreads();
            if (f == 2) break;
            --p;
        }
        if (tid < G_DIM) {
            incl = fmaxf(run, a);
            g_inclusive[(size_t)tile * G_DIM + tid] = incl;
            Spre[tid] = run;
        }
        __threadfence();
        __syncthreads();
        if (tid == 0) atomicExch(&g_flags[tile], 2);
    }
    __syncthreads();

    // ---- combine with tile prefix, stream out ----
    float4* out4 = (float4*)(out + (size_t)tile * TILE_ROWS * G_DIM);
    #pragma unroll
    for (int i = 0; i < 16; ++i) {
        int e = tid + i * 256;                    // 0..4095 float4
        int r = e >> 5, c4 = e & 31;
        const float* s  = &Ssc[r * SSC_PITCH + c4 * 4];
        const float* pp = &Spre[c4 * 4];
        float4 o;
        o.x = fmaxf(s[0], pp[0]);
        o.y = fmaxf(s[1], pp[1]);
        o.z = fmaxf(s[2], pp[2]);
        o.w = fmaxf(s[3], pp[3]);
        out4[e] = o;
    }
    if (write_tail && tile == NUM_TILES - 1 && tid < G_DIM)
        out[(size_t)W_TOTAL * G_DIM + tid] = incl;
}

extern "C" void kernel_launch(void* const* d_in, const int* in_sizes, int n_in,
                              void* d_out, int out_size) {
    const float* local = (const float*)d_in[0];  // [262144, 512]
    const float* gfeat = (const float*)d_in[1];  // [1, 128]
    const float* W1    = (const float*)d_in[2];  // [512, 128]
    const float* b1    = (const float*)d_in[3];  // [128]
    float* out = (float*)d_out;

    static int configured = 0;
    if (!configured) {
        cudaFuncSetAttribute(key_pool_mma,
                             cudaFuncAttributeMaxDynamicSharedMemorySize, SMEM_TOTAL);
        configured = 1;
    }
    int write_tail = (out_size >= W_TOTAL * G_DIM + G_DIM) ? 1 : 0;

    prep_kernel<<<256, 256>>>(W1);
    key_pool_mma<<<NUM_TILES, 256, SMEM_TOTAL>>>(local, gfeat, b1, out, write_tail);
}